// round 13
// baseline (speedup 1.0000x reference)
#include <cuda_runtime.h>
#include <cstdint>
#include <math_constants.h>

// feat [N, C, 16, 8], scoremap [N, 13, 16, 8], conf [N, 13]
#define KP        13
#define HW        128       // 16*8 spatial
#define CPB       256       // channels per tile (2 per thread)
#define THREADS   128
#define NCH       4         // chunks per tile (32 spatial floats each)
#define NBLOCKS   444       // 148 SMs x 3 blocks -> exactly one wave

#define SC_BYTES   (KP * 64 * 8)           // 6656 (k-major raw score, u64[13][64])
#define BUF_BYTES  (CPB * 32 * 4)          // 32768 per buffer (128B per channel row)
#define SMEM_BYTES (SC_BYTES + 2 * BUF_BYTES)   // 72192 -> 3 blocks/SM

// ---------- f32x2 helpers (Blackwell packed fp32) ----------
__device__ __forceinline__ unsigned long long pack2(float a, float b) {
    unsigned long long r;
    asm("mov.b64 %0, {%1, %2};" : "=l"(r) : "f"(a), "f"(b));
    return r;
}
__device__ __forceinline__ float2 unpack2(unsigned long long v) {
    float2 f;
    asm("mov.b64 {%0, %1}, %2;" : "=f"(f.x), "=f"(f.y) : "l"(v));
    return f;
}
__device__ __forceinline__ unsigned long long fma2(unsigned long long a,
                                                   unsigned long long b,
                                                   unsigned long long c) {
    unsigned long long d;
    asm("fma.rn.f32x2 %0, %1, %2, %3;" : "=l"(d) : "l"(a), "l"(b), "l"(c));
    return d;
}
__device__ __forceinline__ unsigned long long add2(unsigned long long a,
                                                   unsigned long long b) {
    unsigned long long d;
    asm("add.rn.f32x2 %0, %1, %2;" : "=l"(d) : "l"(a), "l"(b));
    return d;
}
__device__ __forceinline__ uint32_t smem_u32(const void* p) {
    return (uint32_t)__cvta_generic_to_shared(p);
}
__device__ __forceinline__ void cp16(uint32_t dst, const float4* src) {
    asm volatile("cp.async.cg.shared.global [%0], [%1], 16;"
                 :: "r"(dst), "l"(src) : "memory");
}
__device__ __forceinline__ void cp_commit() {
    asm volatile("cp.async.commit_group;" ::: "memory");
}
__device__ __forceinline__ void cp_wait1() {
    asm volatile("cp.async.wait_group 1;" ::: "memory");
}
__device__ __forceinline__ float4 lds128(uint32_t a) {
    float4 v;
    asm volatile("ld.shared.v4.f32 {%0,%1,%2,%3}, [%4];"
                 : "=f"(v.x), "=f"(v.y), "=f"(v.z), "=f"(v.w) : "r"(a));
    return v;
}
__device__ __forceinline__ ulonglong2 lds128u(uint32_t a) {
    ulonglong2 v;
    asm volatile("ld.shared.v2.u64 {%0,%1}, [%2];"
                 : "=l"(v.x), "=l"(v.y) : "r"(a));
    return v;
}

// 16 cp16s for one feat chunk (constant per-thread geometry, 2 pointer adds/iter)
__device__ __forceinline__ void issue_feat(uint32_t dst, const float4* src) {
    #pragma unroll
    for (int it = 0; it < 16; it++) {
        cp16(dst, src);
        dst += 16 * 128;          // 16 channel rows of 128B
        src += 16 * (HW / 4);
    }
}
// raw k-major score for one n: 416 float4
__device__ __forceinline__ void issue_score(uint32_t sc_base, const float4* gsc4, int tid) {
    #pragma unroll
    for (int it = 0; it < 4; it++) {
        int p = tid + it * THREADS;
        if (p < KP * HW / 4) cp16(sc_base + p * 16, gsc4 + p);
    }
}

__global__ __launch_bounds__(THREADS, 3)
void horeid_kernel(const float* __restrict__ feat,
                   const float* __restrict__ score,
                   const float* __restrict__ conf,
                   float* __restrict__ out_feat,   // [N, 14, C]
                   float* __restrict__ out_conf,   // [N, 14]
                   int C, int total_tiles)
{
    extern __shared__ unsigned char smem_raw[];
    const uint32_t sc_base  = smem_u32(smem_raw);            // score u64[13][64]
    const uint32_t buf_base = sc_base + SC_BYTES;            // 2 feat buffers

    const int tid = threadIdx.x;
    const int bid = blockIdx.x;

    // contiguous tile range, cblk-minor order: tile = n*8 + cblk
    const int start = (int)(((long long)bid * total_tiles) / NBLOCKS);
    const int end   = (int)(((long long)(bid + 1) * total_tiles) / NBLOCKS);
    if (start >= end) return;

    // per-thread cp.async geometry (invariant): q = tid&7, swizzle constant
    const int qv = tid & 7;
    const int cb = tid >> 3;
    const uint32_t dst0 = cb * 128 + (uint32_t)((qv ^ (cb & 7)) << 4);
    const int srcoff = cb * (HW / 4) + qv;

    const float4* feat4  = (const float4*)feat;
    const float4* score4 = (const float4*)score;

    // ---- prologue: score(n of first tile) + feat chunk 0 | feat chunk 1 ----
    {
        const int n0  = start >> 3;
        const int c00 = (start & 7) * CPB;
        const float4* tb = feat4 + ((size_t)n0 * C + c00) * (HW / 4) + srcoff;
        issue_score(sc_base, score4 + (size_t)n0 * (KP * HW / 4), tid);
        issue_feat(buf_base + dst0, tb);
        cp_commit();                                  // group: score + F(ch0)
        issue_feat(buf_base + BUF_BYTES + dst0, tb + 8);
        cp_commit();                                  // group: F(ch1)
    }

    for (int t = start; t < end; t++) {
        const int n  = t >> 3;
        const int c0 = (t & 7) * CPB;

        // conf normalization: owned by the cblk==0 tile of each n
        if ((t & 7) == 0 && tid == 0) {
            const float* cp = conf + (size_t)n * KP;
            float s = 0.0f;
            #pragma unroll
            for (int k = 0; k < KP; k++) s += fabsf(cp[k]);
            s = fmaxf(s, 1e-12f);
            float* oc = out_conf + (size_t)n * (KP + 1);
            #pragma unroll
            for (int k = 0; k < KP; k++) oc[k] = cp[k] / s;
            oc[KP] = 1.0f;
        }

        unsigned long long accA[KP], accB[KP];
        #pragma unroll
        for (int k = 0; k < KP; k++) { accA[k] = 0ull; accB[k] = 0ull; }
        unsigned long long sumA = 0ull, sumB = 0ull;
        float2 mxA = make_float2(-CUDART_INF_F, -CUDART_INF_F);
        float2 mxB = make_float2(-CUDART_INF_F, -CUDART_INF_F);

        #pragma unroll
        for (int ch = 0; ch < NCH; ch++) {
            cp_wait1();             // chunk (t,ch) landed; next chunk may be in flight
            __syncthreads();

            const uint32_t bb   = buf_base + (ch & 1) * BUF_BYTES;
            const uint32_t rowA = bb + tid * 128;
            const uint32_t scc  = sc_base + ch * 128;

            #pragma unroll
            for (int q = 0; q < 8; q++) {                   // 2 sp-pairs per q
                uint32_t a = rowA + (uint32_t)((q ^ qv) << 4);
                float4 fa = lds128(a);
                float4 fb = lds128(a + 128 * 128);          // channel B row
                unsigned long long fa0 = pack2(fa.x, fa.y), fa1 = pack2(fa.z, fa.w);
                unsigned long long fb0 = pack2(fb.x, fb.y), fb1 = pack2(fb.z, fb.w);

                const uint32_t sq = scc + (uint32_t)(q << 4);
                #pragma unroll
                for (int k = 0; k < KP; k++) {
                    ulonglong2 s = lds128u(sq + k * 512);   // scores (sp0, sp0+1)
                    accA[k] = fma2(fa0, s.x, accA[k]);
                    accA[k] = fma2(fa1, s.y, accA[k]);
                    accB[k] = fma2(fb0, s.x, accB[k]);
                    accB[k] = fma2(fb1, s.y, accB[k]);
                }

                sumA = add2(sumA, add2(fa0, fa1));
                sumB = add2(sumB, add2(fb0, fb1));
                mxA.x = fmaxf(mxA.x, fmaxf(fa.x, fa.z));
                mxA.y = fmaxf(mxA.y, fmaxf(fa.y, fa.w));
                mxB.x = fmaxf(mxB.x, fmaxf(fb.x, fb.z));
                mxB.y = fmaxf(mxB.y, fmaxf(fb.y, fb.w));
            }

            __syncthreads();        // all reads of buf[ch&1] (and old score) done

            // issue chunk (t,ch)+2: (t, ch+2) for ch<2, else (t+1, ch-2)
            const int t2  = (ch < 2) ? t : t + 1;
            if (t2 < end) {
                const int ch2 = (ch < 2) ? ch + 2 : ch - 2;
                // n-transition: next compute is (t+1, ch0) with a new n ->
                // its score must be a SEPARATE, earlier group than F(t+1,ch1)
                if (ch == 3 && ((t + 1) & 7) == 0) {
                    issue_score(sc_base,
                                score4 + (size_t)((t + 1) >> 3) * (KP * HW / 4), tid);
                    cp_commit();
                }
                const int n2  = t2 >> 3;
                const int c02 = (t2 & 7) * CPB;
                issue_feat(bb + dst0,
                           feat4 + ((size_t)n2 * C + c02) * (HW / 4) + srcoff + ch2 * 8);
            }
            cp_commit();            // empty groups at tail keep wait counts uniform
        }

        // ---- per-tile epilogue (next tile's loads already in flight) ----
        const int cA = c0 + tid;
        const int cB = cA + 128;
        float* op = out_feat + (size_t)n * (KP + 1) * C;
        #pragma unroll
        for (int k = 0; k < KP; k++) {
            float2 a = unpack2(accA[k]);
            float2 b = unpack2(accB[k]);
            op[(size_t)k * C + cA] = a.x + a.y;
            op[(size_t)k * C + cB] = b.x + b.y;
        }
        float2 sa = unpack2(sumA), sb = unpack2(sumB);
        op[(size_t)KP * C + cA] = (sa.x + sa.y) * (1.0f / (float)HW) + fmaxf(mxA.x, mxA.y);
        op[(size_t)KP * C + cB] = (sb.x + sb.y) * (1.0f / (float)HW) + fmaxf(mxB.x, mxB.y);
    }
}

extern "C" void kernel_launch(void* const* d_in, const int* in_sizes, int n_in,
                              void* d_out, int out_size)
{
    const float* feat  = (const float*)d_in[0];
    const float* score = (const float*)d_in[1];
    const float* conf  = (const float*)d_in[2];
    float* out = (float*)d_out;

    const int N = in_sizes[2] / KP;                 // 256
    const int C = in_sizes[0] / ((size_t)N * HW);   // 2048
    const int total_tiles = N * (C / CPB);          // 2048

    float* out_feat = out;
    float* out_conf = out + (size_t)N * (KP + 1) * C;

    cudaFuncSetAttribute(horeid_kernel,
                         cudaFuncAttributeMaxDynamicSharedMemorySize, SMEM_BYTES);

    horeid_kernel<<<NBLOCKS, THREADS, SMEM_BYTES>>>(feat, score, conf,
                                                    out_feat, out_conf,
                                                    C, total_tiles);
}